// round 12
// baseline (speedup 1.0000x reference)
#include <cuda_runtime.h>
#include <math.h>

#define N_NODES  50000
#define N_EDGES  800000
#define NODE_DIM 64
#define EDGE_DIM 32
#define HID      128
#define EPG      16            // edges per warp-group iteration (phase-2 amortization)
#define TPB      192           // 6 warps, 2 blocks/SM -> 170-reg cap (headroom vs ~110 used)
#define WPB      (TPB / 32)
#define NB       8192          // table bins over d in [0,15], nearest-neighbor
#define TB_BINS  8

typedef unsigned long long ull;

// Per-node precomputed rows [ns(128) | nd(128) | cs(128) | cd(128)]
__device__ float g_A[(size_t)N_NODES * 512];
// Folded edge-path weights (used only to build the table)
__device__ float g_Mn[32 * 128];
__device__ float g_Mc[32 * 128];
__device__ float g_bn[128];
__device__ float g_bc[128];
// Table: row i = [F(d_i)+bn (128) | G(d_i)+bc (128)], d_i = i*15/NB
__device__ float g_T[(size_t)(NB + 1) * 256];
// Rearranged Wn2: WA[i*32+l] = Wn2[4i..4i+3][2l], WB same for 2l+1
__device__ float4 g_WA[1024];
__device__ float4 g_WB[1024];

union F4 { float4 f; ulonglong2 u; };
union F2 { float2 f; ull u; };

__device__ __forceinline__ ull pk2(float x, float y) {
    ull r; asm("mov.b64 %0,{%1,%2};" : "=l"(r) : "f"(x), "f"(y)); return r;
}
__device__ __forceinline__ void upk2(ull v, float& x, float& y) {
    asm("mov.b64 {%0,%1},%2;" : "=f"(x), "=f"(y) : "l"(v));
}
__device__ __forceinline__ ull ffma2(ull a, ull b, ull c) {
    ull d; asm("fma.rn.f32x2 %0,%1,%2,%3;" : "=l"(d) : "l"(a), "l"(b), "l"(c)); return d;
}
__device__ __forceinline__ ull fadd2(ull a, ull b) {
    ull d; asm("add.rn.f32x2 %0,%1,%2;" : "=l"(d) : "l"(a), "l"(b)); return d;
}
// silu via MUFU tanh: silu(z) = hz + hz*tanh(hz), hz = z/2
__device__ __forceinline__ float silu1(float z) {
    float hz = 0.5f * z;
    float th;
    asm("tanh.approx.f32 %0, %1;" : "=f"(th) : "f"(hz));
    return fmaf(hz, th, hz);
}

// ---------------------------------------------------------------------------
// K0: fold edge-path weights + rearrange Wn2
// ---------------------------------------------------------------------------
__global__ void k_fold(const float* __restrict__ We2, const float* __restrict__ be2,
                       const float* __restrict__ Wn1, const float* __restrict__ bn1,
                       const float* __restrict__ Wc1, const float* __restrict__ bc1,
                       const float* __restrict__ Wn2) {
    int j = threadIdx.x;  // 0..127
    float bn = bn1[j], bc = bc1[j];
    for (int b = 0; b < 32; b++) {
        bn += be2[b] * Wn1[(128 + b) * 128 + j];
        bc += be2[b] * Wc1[(128 + b) * 128 + j];
    }
    g_bn[j] = bn;
    g_bc[j] = bc;
    for (int a = 0; a < 32; a++) {
        float sn = 0.f, sc = 0.f;
        for (int b = 0; b < 32; b++) {
            float w = We2[a * 32 + b];
            sn += w * Wn1[(128 + b) * 128 + j];
            sc += w * Wc1[(128 + b) * 128 + j];
        }
        g_Mn[a * 128 + j] = sn;
        g_Mc[a * 128 + j] = sc;
    }
    for (int idx = j; idx < 1024; idx += 128) {
        int i = idx >> 5, l = idx & 31;
        g_WA[idx] = make_float4(Wn2[(4 * i + 0) * 64 + 2 * l], Wn2[(4 * i + 1) * 64 + 2 * l],
                                Wn2[(4 * i + 2) * 64 + 2 * l], Wn2[(4 * i + 3) * 64 + 2 * l]);
        g_WB[idx] = make_float4(Wn2[(4 * i + 0) * 64 + 2 * l + 1], Wn2[(4 * i + 1) * 64 + 2 * l + 1],
                                Wn2[(4 * i + 2) * 64 + 2 * l + 1], Wn2[(4 * i + 3) * 64 + 2 * l + 1]);
    }
}

// ---------------------------------------------------------------------------
// K0b: build edge-path table. TB_BINS bins per block, smem-staged M.
// ---------------------------------------------------------------------------
__global__ void k_tab(const float* __restrict__ We1, const float* __restrict__ be1) {
    __shared__ float M_sh[8192];   // Mn(4096) | Mc(4096)
    __shared__ float b_sh[256];    // bn(128) | bc(128)
    __shared__ float t_sh[32];
    int j = threadIdx.x;           // 0..255
    for (int i = j; i < 4096; i += 256) {
        M_sh[i]        = g_Mn[i];
        M_sh[4096 + i] = g_Mc[i];
    }
    if (j < 128) {
        b_sh[j]       = g_bn[j];
        b_sh[128 + j] = g_bc[j];
    }
    __syncthreads();

    const float* M = (j < 128) ? M_sh : (M_sh + 4096);
    int jj = j & 127;
    float bb = b_sh[j];

    for (int bi = 0; bi < TB_BINS; bi++) {
        int i = blockIdx.x * TB_BINS + bi;
        if (i > NB) break;
        float d = (15.0f / NB) * i;
        if (j < 32) {
            float z = d * We1[j] + be1[j];
            t_sh[j] = z / (1.f + __expf(-z));   // exact silu for table accuracy
        }
        __syncthreads();
        float s = bb;
#pragma unroll 8
        for (int k = 0; k < 32; k++) s += t_sh[k] * M[k * 128 + jj];
        g_T[(size_t)i * 256 + j] = s;
        __syncthreads();
    }
}

// ---------------------------------------------------------------------------
// K1: per-node precompute, f32x2 math. 128 threads, NPB=16 (round-7 proven).
// ---------------------------------------------------------------------------
#define NPB 16
__global__ void k_node(const float* __restrict__ h,
                       const float* __restrict__ Wn1,
                       const float* __restrict__ Wc1) {
    __shared__ ull h2[NPB * 64];   // duplicated {h,h} pairs
    int node0 = blockIdx.x * NPB;
    for (int i = threadIdx.x; i < NPB * 64; i += 128) {
        float hv = h[node0 * 64 + i];
        h2[i] = pk2(hv, hv);
    }
    __syncthreads();
    int j = threadIdx.x;
    int m = j >> 5;
    int c = (j & 31) * 4;
    const float* W = ((m & 2) ? Wc1 : Wn1) + ((m & 1) ? 64 * 128 : 0);

    ull a0[NPB], a1[NPB];
#pragma unroll
    for (int n = 0; n < NPB; n++) { a0[n] = 0ull; a1[n] = 0ull; }
#pragma unroll 4
    for (int k = 0; k < 64; k++) {
        F4 w; w.f = *(const float4*)&W[k * 128 + c];
#pragma unroll
        for (int n = 0; n < NPB; n++) {
            ull hv = h2[n * 64 + k];
            a0[n] = ffma2(hv, w.u.x, a0[n]);
            a1[n] = ffma2(hv, w.u.y, a1[n]);
        }
    }
#pragma unroll
    for (int n = 0; n < NPB; n++) {
        F4 r; r.u.x = a0[n]; r.u.y = a1[n];
        *(float4*)&g_A[(size_t)(node0 + n) * 512 + m * 128 + c] = r.f;
    }
}

// ---------------------------------------------------------------------------
// K2: initialize output with (h, x), float4-vectorized
// ---------------------------------------------------------------------------
__global__ void k_init(const float4* __restrict__ h4, const float4* __restrict__ x4,
                       float4* __restrict__ out4) {
    const int nh4  = N_NODES * 16;          // 800000
    const int tot4 = nh4 + N_NODES * 3 / 4; // 837500
    for (int i = blockIdx.x * blockDim.x + threadIdx.x; i < tot4; i += gridDim.x * blockDim.x)
        out4[i] = (i < nh4) ? h4[i] : x4[i - nh4];
}

// ---------------------------------------------------------------------------
// K3: edge kernel. NN-table edge path; EPG=16 edges per phase-2 weight pass.
// ---------------------------------------------------------------------------
__global__ void __launch_bounds__(TPB, 2)
k_edge(const float* __restrict__ dist,
       const int*   __restrict__ eidx,
       const float* __restrict__ x,
       const float* __restrict__ bn2,
       const float* __restrict__ Wc2,
       float* __restrict__ out) {
    extern __shared__ float sm[];
    float4* WA_sh = (float4*)sm;               // 1024 f4 = 16KB
    float4* WB_sh = WA_sh + 1024;              // 16KB
    float*  gbuf  = (float*)(WB_sh + 1024);    // WPB warps * 2048 floats (8KB/warp)
    float*  Wc2_sh = gbuf + WPB * 2048;        // 128
    float*  bn2_sh = Wc2_sh + 128;             // 64

    for (int i = threadIdx.x; i < 1024; i += blockDim.x) {
        WA_sh[i] = g_WA[i];
        WB_sh[i] = g_WB[i];
    }
    if (threadIdx.x < 128) Wc2_sh[threadIdx.x] = Wc2[threadIdx.x];
    if (threadIdx.x < 64)  bn2_sh[threadIdx.x] = bn2[threadIdx.x];
    __syncthreads();

    const int lane = threadIdx.x & 31;
    const int wib  = threadIdx.x >> 5;
    const int gw   = blockIdx.x * WPB + wib;
    const int nw   = gridDim.x * WPB;

    F4 wc2_4; wc2_4.f = *(const float4*)&Wc2_sh[4 * lane];
    const float2 bn2_2 = *(const float2*)&bn2_sh[2 * lane];
    float* gb = gbuf + wib * 2048;
    const float4* A4 = (const float4*)g_A;
    const float4* T4 = (const float4*)g_T;     // 64 f4 per table row
    const float4* gb4 = (const float4*)gb;
    float* out_x = out + (size_t)N_NODES * 64;

    for (int base = gw * EPG; base < N_EDGES; base += nw * EPG) {

        // ---- phase 1: two halves of 8 edges (proven structure per half) ----
#pragma unroll 1
        for (int hf = 0; hf < 2; hf++) {
            int src8[8], dst8[8];
            float cw[8];
#pragma unroll
            for (int ee = 0; ee < 8; ee++) {
                int e = base + hf * 8 + ee;
                float d = dist[e];
                int s  = eidx[e];
                int dd = eidx[N_EDGES + e];
                src8[ee] = s; dst8[ee] = dd;

                float p = d * (NB / 15.0f) + 0.5f;
                int i0 = (int)p;
                i0 = max(0, min(i0, NB));
                const float4* t0 = T4 + (size_t)i0 * 64;

                // node-MLP hidden: pn = A_ns[src] + A_nd[dst] + F(d)
                {
                    F4 a;  a.f  = A4[(size_t)s  * 128 + lane];
                    F4 b;  b.f  = A4[(size_t)dd * 128 + 32 + lane];
                    F4 f0; f0.f = t0[lane];
                    ull px = fadd2(fadd2(a.u.x, b.u.x), f0.u.x);
                    ull py = fadd2(fadd2(a.u.y, b.u.y), f0.u.y);
                    float p0, p1, p2, p3;
                    upk2(px, p0, p1);
                    upk2(py, p2, p3);
                    float4 gn = make_float4(silu1(p0), silu1(p1), silu1(p2), silu1(p3));
                    *(float4*)&gb[(hf * 8 + ee) * 128 + 4 * lane] = gn;
                }
                // coord-MLP hidden -> scalar cw
                {
                    F4 c;  c.f  = A4[(size_t)s  * 128 + 64 + lane];
                    F4 dv; dv.f = A4[(size_t)dd * 128 + 96 + lane];
                    F4 g0; g0.f = t0[32 + lane];
                    ull px = fadd2(fadd2(c.u.x, dv.u.x), g0.u.x);
                    ull py = fadd2(fadd2(c.u.y, dv.u.y), g0.u.y);
                    float p0, p1, p2, p3;
                    upk2(px, p0, p1);
                    upk2(py, p2, p3);
                    float ss = silu1(p0) * wc2_4.f.x + silu1(p1) * wc2_4.f.y
                             + silu1(p2) * wc2_4.f.z + silu1(p3) * wc2_4.f.w;
#pragma unroll
                    for (int off = 16; off > 0; off >>= 1)
                        ss += __shfl_xor_sync(0xffffffffu, ss, off);
                    cw[ee] = ss;
                }
            }

            // coord scatter (lanes 0..7, one edge each)
            if (lane < 8) {
                float mycw = cw[0]; int ms = src8[0], md = dst8[0];
#pragma unroll
                for (int ee = 1; ee < 8; ee++)
                    if (lane == ee) { mycw = cw[ee]; ms = src8[ee]; md = dst8[ee]; }
                float dx = x[ms * 3 + 0] - x[md * 3 + 0];
                float dy = x[ms * 3 + 1] - x[md * 3 + 1];
                float dz = x[ms * 3 + 2] - x[md * 3 + 2];
                float len = fmaxf(sqrtf(dx * dx + dy * dy + dz * dz), 1e-8f);
                float inv = mycw / len;
                float* ox = out_x + (size_t)md * 3;
                atomicAdd(&ox[0], dx * inv);
                atomicAdd(&ox[1], dy * inv);
                atomicAdd(&ox[2], dz * inv);
            }
            __syncwarp();
        }

        // ---- phase 2: gn(16 x 128) @ Wn2 -> 16 x 64, one weight pass ----
        ull macA[EPG], macB[EPG];
#pragma unroll
        for (int ee = 0; ee < EPG; ee++) {
            macA[ee] = pk2(bn2_2.x, 0.f);
            macB[ee] = pk2(bn2_2.y, 0.f);
        }
#pragma unroll 2
        for (int i = 0; i < 32; i++) {
            F4 wA; wA.f = WA_sh[i * 32 + lane];
            F4 wB; wB.f = WB_sh[i * 32 + lane];
#pragma unroll
            for (int ee = 0; ee < EPG; ee++) {
                F4 g; g.f = gb4[ee * 32 + i];  // broadcast
                macA[ee] = ffma2(g.u.x, wA.u.x, macA[ee]);
                macA[ee] = ffma2(g.u.y, wA.u.y, macA[ee]);
                macB[ee] = ffma2(g.u.x, wB.u.x, macB[ee]);
                macB[ee] = ffma2(g.u.y, wB.u.y, macB[ee]);
            }
        }

        // ---- node message scatter; dst reloaded (uniform, L1-hot) ----
#pragma unroll
        for (int ee = 0; ee < EPG; ee++) {
            int dd = eidx[N_EDGES + base + ee];
            float a0, a1, b0, b1;
            upk2(macA[ee], a0, a1);
            upk2(macB[ee], b0, b1);
            float* oh = out + (size_t)dd * 64;
            atomicAdd(&oh[2 * lane],     a0 + a1);
            atomicAdd(&oh[2 * lane + 1], b0 + b1);
        }
        __syncwarp();   // gbuf reuse safety across iterations
    }
}

// ---------------------------------------------------------------------------
extern "C" void kernel_launch(void* const* d_in, const int* in_sizes, int n_in,
                              void* d_out, int out_size) {
    const float* h    = (const float*)d_in[0];
    const float* x    = (const float*)d_in[1];
    const float* dist = (const float*)d_in[2];
    const float* We1  = (const float*)d_in[3];
    const float* be1  = (const float*)d_in[4];
    const float* We2  = (const float*)d_in[5];
    const float* be2  = (const float*)d_in[6];
    const float* Wn1  = (const float*)d_in[7];
    const float* bn1  = (const float*)d_in[8];
    const float* Wn2  = (const float*)d_in[9];
    const float* bn2  = (const float*)d_in[10];
    const float* Wc1  = (const float*)d_in[11];
    const float* bc1  = (const float*)d_in[12];
    const float* Wc2  = (const float*)d_in[13];
    const int*   eidx = (const int*)d_in[14];
    float* out = (float*)d_out;

    static bool attr_set = false;
    if (!attr_set) {
        cudaFuncSetAttribute(k_edge, cudaFuncAttributeMaxDynamicSharedMemorySize, 84 * 1024);
        attr_set = true;
    }

    k_fold<<<1, 128>>>(We2, be2, Wn1, bn1, Wc1, bc1, Wn2);
    k_tab<<<(NB + 1 + TB_BINS - 1) / TB_BINS, 256>>>(We1, be1);
    k_node<<<N_NODES / NPB, 128>>>(h, Wn1, Wc1);
    k_init<<<1024, 256>>>((const float4*)h, (const float4*)x, (float4*)out);

    // smem: 8192 (WA,WB) + WPB*2048 (gbuf) + 192 small floats
    const int smem = (8192 + WPB * 2048 + 192) * sizeof(float);  // 82688 B
    k_edge<<<296, TPB, smem>>>(dist, eidx, x, bn2, Wc2, out);
}

// round 13
// speedup vs baseline: 1.1757x; 1.1757x over previous
#include <cuda_runtime.h>
#include <cuda_fp16.h>
#include <math.h>

#define N_NODES  50000
#define N_EDGES  800000
#define NODE_DIM 64
#define EDGE_DIM 32
#define HID      128
#define EPB      8
#define TPB      256
#define WPB      (TPB / 32)
#define NB       8192          // table bins over d in [0,15], nearest-neighbor
#define TB_BINS  8

typedef unsigned long long ull;

// Per-node precomputed rows, fp16: [ns(128) | nd(128) | cs(128) | cd(128)] halves
__device__ __half g_Ah[(size_t)N_NODES * 512];
// Folded edge-path weights (used only to build the table)
__device__ float g_Mn[32 * 128];
__device__ float g_Mc[32 * 128];
__device__ float g_bn[128];
__device__ float g_bc[128];
// Table: row i = [F(d_i)+bn (128) | G(d_i)+bc (128)], d_i = i*15/NB
__device__ float g_T[(size_t)(NB + 1) * 256];
// Rearranged Wn2: WA[i*32+l] = Wn2[4i..4i+3][2l], WB same for 2l+1
__device__ float4 g_WA[1024];
__device__ float4 g_WB[1024];

union F4 { float4 f; ulonglong2 u; };
union F2 { float2 f; ull u; };

__device__ __forceinline__ ull pk2(float x, float y) {
    ull r; asm("mov.b64 %0,{%1,%2};" : "=l"(r) : "f"(x), "f"(y)); return r;
}
__device__ __forceinline__ void upk2(ull v, float& x, float& y) {
    asm("mov.b64 {%0,%1},%2;" : "=f"(x), "=f"(y) : "l"(v));
}
__device__ __forceinline__ ull ffma2(ull a, ull b, ull c) {
    ull d; asm("fma.rn.f32x2 %0,%1,%2,%3;" : "=l"(d) : "l"(a), "l"(b), "l"(c)); return d;
}
__device__ __forceinline__ ull fadd2(ull a, ull b) {
    ull d; asm("add.rn.f32x2 %0,%1,%2;" : "=l"(d) : "l"(a), "l"(b)); return d;
}
// half2 (packed in u32) -> f32x2 pair packed in u64
__device__ __forceinline__ ull h2f2(unsigned int h) {
    ull r;
    asm("{\n\t"
        ".reg .f16 a,b;\n\t"
        ".reg .f32 lo,hi;\n\t"
        "mov.b32 {a,b},%1;\n\t"
        "cvt.f32.f16 lo,a;\n\t"
        "cvt.f32.f16 hi,b;\n\t"
        "mov.b64 %0,{lo,hi};\n\t"
        "}" : "=l"(r) : "r"(h));
    return r;
}
// silu via MUFU tanh: silu(z) = hz + hz*tanh(hz), hz = z/2
__device__ __forceinline__ float silu1(float z) {
    float hz = 0.5f * z;
    float th;
    asm("tanh.approx.f32 %0, %1;" : "=f"(th) : "f"(hz));
    return fmaf(hz, th, hz);
}

// ---------------------------------------------------------------------------
// K0: fold edge-path weights + rearrange Wn2
// ---------------------------------------------------------------------------
__global__ void k_fold(const float* __restrict__ We2, const float* __restrict__ be2,
                       const float* __restrict__ Wn1, const float* __restrict__ bn1,
                       const float* __restrict__ Wc1, const float* __restrict__ bc1,
                       const float* __restrict__ Wn2) {
    int j = threadIdx.x;  // 0..127
    float bn = bn1[j], bc = bc1[j];
    for (int b = 0; b < 32; b++) {
        bn += be2[b] * Wn1[(128 + b) * 128 + j];
        bc += be2[b] * Wc1[(128 + b) * 128 + j];
    }
    g_bn[j] = bn;
    g_bc[j] = bc;
    for (int a = 0; a < 32; a++) {
        float sn = 0.f, sc = 0.f;
        for (int b = 0; b < 32; b++) {
            float w = We2[a * 32 + b];
            sn += w * Wn1[(128 + b) * 128 + j];
            sc += w * Wc1[(128 + b) * 128 + j];
        }
        g_Mn[a * 128 + j] = sn;
        g_Mc[a * 128 + j] = sc;
    }
    for (int idx = j; idx < 1024; idx += 128) {
        int i = idx >> 5, l = idx & 31;
        g_WA[idx] = make_float4(Wn2[(4 * i + 0) * 64 + 2 * l], Wn2[(4 * i + 1) * 64 + 2 * l],
                                Wn2[(4 * i + 2) * 64 + 2 * l], Wn2[(4 * i + 3) * 64 + 2 * l]);
        g_WB[idx] = make_float4(Wn2[(4 * i + 0) * 64 + 2 * l + 1], Wn2[(4 * i + 1) * 64 + 2 * l + 1],
                                Wn2[(4 * i + 2) * 64 + 2 * l + 1], Wn2[(4 * i + 3) * 64 + 2 * l + 1]);
    }
}

// ---------------------------------------------------------------------------
// K0b: build edge-path table. TB_BINS bins per block, smem-staged M.
// ---------------------------------------------------------------------------
__global__ void k_tab(const float* __restrict__ We1, const float* __restrict__ be1) {
    __shared__ float M_sh[8192];   // Mn(4096) | Mc(4096)
    __shared__ float b_sh[256];    // bn(128) | bc(128)
    __shared__ float t_sh[32];
    int j = threadIdx.x;           // 0..255
    for (int i = j; i < 4096; i += 256) {
        M_sh[i]        = g_Mn[i];
        M_sh[4096 + i] = g_Mc[i];
    }
    if (j < 128) {
        b_sh[j]       = g_bn[j];
        b_sh[128 + j] = g_bc[j];
    }
    __syncthreads();

    const float* M = (j < 128) ? M_sh : (M_sh + 4096);
    int jj = j & 127;
    float bb = b_sh[j];

    for (int bi = 0; bi < TB_BINS; bi++) {
        int i = blockIdx.x * TB_BINS + bi;
        if (i > NB) break;
        float d = (15.0f / NB) * i;
        if (j < 32) {
            float z = d * We1[j] + be1[j];
            t_sh[j] = z / (1.f + __expf(-z));   // exact silu for table accuracy
        }
        __syncthreads();
        float s = bb;
#pragma unroll 8
        for (int k = 0; k < 32; k++) s += t_sh[k] * M[k * 128 + jj];
        g_T[(size_t)i * 256 + j] = s;
        __syncthreads();
    }
}

// ---------------------------------------------------------------------------
// K1: per-node precompute, f32x2 math, fp16 output. 128 thr, NPB=16 (proven).
// ---------------------------------------------------------------------------
#define NPB 16
__global__ void k_node(const float* __restrict__ h,
                       const float* __restrict__ Wn1,
                       const float* __restrict__ Wc1) {
    __shared__ ull h2[NPB * 64];   // duplicated {h,h} pairs
    int node0 = blockIdx.x * NPB;
    for (int i = threadIdx.x; i < NPB * 64; i += 128) {
        float hv = h[node0 * 64 + i];
        h2[i] = pk2(hv, hv);
    }
    __syncthreads();
    int j = threadIdx.x;
    int m = j >> 5;
    int c = (j & 31) * 4;
    const float* W = ((m & 2) ? Wc1 : Wn1) + ((m & 1) ? 64 * 128 : 0);

    ull a0[NPB], a1[NPB];
#pragma unroll
    for (int n = 0; n < NPB; n++) { a0[n] = 0ull; a1[n] = 0ull; }
#pragma unroll 4
    for (int k = 0; k < 64; k++) {
        F4 w; w.f = *(const float4*)&W[k * 128 + c];
#pragma unroll
        for (int n = 0; n < NPB; n++) {
            ull hv = h2[n * 64 + k];
            a0[n] = ffma2(hv, w.u.x, a0[n]);
            a1[n] = ffma2(hv, w.u.y, a1[n]);
        }
    }
#pragma unroll
    for (int n = 0; n < NPB; n++) {
        float x0, x1, x2, x3;
        upk2(a0[n], x0, x1);
        upk2(a1[n], x2, x3);
        __half2 hA = __float22half2_rn(make_float2(x0, x1));
        __half2 hB = __float22half2_rn(make_float2(x2, x3));
        uint2 st;
        st.x = *(unsigned int*)&hA;
        st.y = *(unsigned int*)&hB;
        *(uint2*)&g_Ah[(size_t)(node0 + n) * 512 + m * 128 + c] = st;
    }
}

// ---------------------------------------------------------------------------
// K2: initialize output with (h, x), float4-vectorized
// ---------------------------------------------------------------------------
__global__ void k_init(const float4* __restrict__ h4, const float4* __restrict__ x4,
                       float4* __restrict__ out4) {
    const int nh4  = N_NODES * 16;          // 800000
    const int tot4 = nh4 + N_NODES * 3 / 4; // 837500
    for (int i = blockIdx.x * blockDim.x + threadIdx.x; i < tot4; i += gridDim.x * blockDim.x)
        out4[i] = (i < nh4) ? h4[i] : x4[i - nh4];
}

// ---------------------------------------------------------------------------
// K3: edge kernel. NN-table + fp16 A-gathers (L2-resident working set).
// ---------------------------------------------------------------------------
__global__ void __launch_bounds__(TPB, 2)
k_edge(const float* __restrict__ dist,
       const int*   __restrict__ eidx,
       const float* __restrict__ x,
       const float* __restrict__ bn2,
       const float* __restrict__ Wc2,
       float* __restrict__ out) {
    extern __shared__ float sm[];
    float4* WA_sh = (float4*)sm;               // 1024 f4
    float4* WB_sh = WA_sh + 1024;              // 1024 f4
    float*  gbuf  = (float*)(WB_sh + 1024);    // WPB warps * 1024
    float*  Wc2_sh = gbuf + WPB * 1024;        // 128
    float*  bn2_sh = Wc2_sh + 128;             // 64

    for (int i = threadIdx.x; i < 1024; i += blockDim.x) {
        WA_sh[i] = g_WA[i];
        WB_sh[i] = g_WB[i];
    }
    if (threadIdx.x < 128) Wc2_sh[threadIdx.x] = Wc2[threadIdx.x];
    if (threadIdx.x < 64)  bn2_sh[threadIdx.x] = bn2[threadIdx.x];
    __syncthreads();

    const int lane = threadIdx.x & 31;
    const int wib  = threadIdx.x >> 5;
    const int gw   = blockIdx.x * WPB + wib;
    const int nw   = gridDim.x * WPB;

    F4 wc2_4; wc2_4.f = *(const float4*)&Wc2_sh[4 * lane];
    const float2 bn2_2 = *(const float2*)&bn2_sh[2 * lane];
    float* gb = gbuf + wib * 1024;
    const uint2*  A2 = (const uint2*)g_Ah;     // 128 uint2 per node row
    const float4* T4 = (const float4*)g_T;     // 64 f4 per table row
    const float4* gb4 = (const float4*)gb;
    float* out_x = out + (size_t)N_NODES * 64;

    for (int base = gw * EPB; base < N_EDGES; base += nw * EPB) {
        int src[EPB], dstn[EPB];
        float cw[EPB];

        // ---- per-edge: nearest-table edge path + fp16 node-term gathers ----
#pragma unroll
        for (int ee = 0; ee < EPB; ee++) {
            int e = base + ee;
            float d = dist[e];
            int s  = eidx[e];
            int dd = eidx[N_EDGES + e];
            src[ee] = s; dstn[ee] = dd;

            float p = d * (NB / 15.0f) + 0.5f;
            int i0 = (int)p;
            i0 = max(0, min(i0, NB));
            const float4* t0 = T4 + (size_t)i0 * 64;

            // node-MLP hidden: pn = A_ns[src] + A_nd[dst] + F(d)
            {
                uint2 av = A2[(size_t)s  * 128 + lane];
                uint2 bv = A2[(size_t)dd * 128 + 32 + lane];
                F4 f0; f0.f = t0[lane];
                ull px = fadd2(fadd2(h2f2(av.x), h2f2(bv.x)), f0.u.x);
                ull py = fadd2(fadd2(h2f2(av.y), h2f2(bv.y)), f0.u.y);
                float p0, p1, p2, p3;
                upk2(px, p0, p1);
                upk2(py, p2, p3);
                float4 gn = make_float4(silu1(p0), silu1(p1), silu1(p2), silu1(p3));
                *(float4*)&gb[ee * 128 + 4 * lane] = gn;
            }
            // coord-MLP hidden -> scalar cw
            {
                uint2 cv = A2[(size_t)s  * 128 + 64 + lane];
                uint2 dv = A2[(size_t)dd * 128 + 96 + lane];
                F4 g0; g0.f = t0[32 + lane];
                ull px = fadd2(fadd2(h2f2(cv.x), h2f2(dv.x)), g0.u.x);
                ull py = fadd2(fadd2(h2f2(cv.y), h2f2(dv.y)), g0.u.y);
                float p0, p1, p2, p3;
                upk2(px, p0, p1);
                upk2(py, p2, p3);
                float ss = silu1(p0) * wc2_4.f.x + silu1(p1) * wc2_4.f.y
                         + silu1(p2) * wc2_4.f.z + silu1(p3) * wc2_4.f.w;
#pragma unroll
                for (int off = 16; off > 0; off >>= 1)
                    ss += __shfl_xor_sync(0xffffffffu, ss, off);
                cw[ee] = ss;
            }
        }

        // ---- coord scatter (lanes 0..7, one edge each) ----
        if (lane < EPB) {
            float mycw = cw[0]; int ms = src[0], md = dstn[0];
#pragma unroll
            for (int ee = 1; ee < EPB; ee++)
                if (lane == ee) { mycw = cw[ee]; ms = src[ee]; md = dstn[ee]; }
            float dx = x[ms * 3 + 0] - x[md * 3 + 0];
            float dy = x[ms * 3 + 1] - x[md * 3 + 1];
            float dz = x[ms * 3 + 2] - x[md * 3 + 2];
            float len = fmaxf(sqrtf(dx * dx + dy * dy + dz * dz), 1e-8f);
            float inv = mycw / len;
            float* ox = out_x + (size_t)md * 3;
            atomicAdd(&ox[0], dx * inv);
            atomicAdd(&ox[1], dy * inv);
            atomicAdd(&ox[2], dz * inv);
        }
        __syncwarp();

        // ---- phase 2: gn(128) @ Wn2 -> 64 ----
        ull macA[EPB], macB[EPB];
#pragma unroll
        for (int ee = 0; ee < EPB; ee++) {
            macA[ee] = pk2(bn2_2.x, 0.f);
            macB[ee] = pk2(bn2_2.y, 0.f);
        }
#pragma unroll
        for (int i = 0; i < 32; i++) {
            F4 wA; wA.f = WA_sh[i * 32 + lane];
            F4 wB; wB.f = WB_sh[i * 32 + lane];
#pragma unroll
            for (int ee = 0; ee < EPB; ee++) {
                F4 g; g.f = gb4[ee * 32 + i];  // broadcast
                macA[ee] = ffma2(g.u.x, wA.u.x, macA[ee]);
                macA[ee] = ffma2(g.u.y, wA.u.y, macA[ee]);
                macB[ee] = ffma2(g.u.x, wB.u.x, macB[ee]);
                macB[ee] = ffma2(g.u.y, wB.u.y, macB[ee]);
            }
        }

        // ---- node message scatter (scalar atomics: proven REDG fast path) ----
#pragma unroll
        for (int ee = 0; ee < EPB; ee++) {
            float a0, a1, b0, b1;
            upk2(macA[ee], a0, a1);
            upk2(macB[ee], b0, b1);
            float* oh = out + (size_t)dstn[ee] * 64;
            atomicAdd(&oh[2 * lane],     a0 + a1);
            atomicAdd(&oh[2 * lane + 1], b0 + b1);
        }
        __syncwarp();   // gbuf reuse safety across iterations
    }
}

// ---------------------------------------------------------------------------
extern "C" void kernel_launch(void* const* d_in, const int* in_sizes, int n_in,
                              void* d_out, int out_size) {
    const float* h    = (const float*)d_in[0];
    const float* x    = (const float*)d_in[1];
    const float* dist = (const float*)d_in[2];
    const float* We1  = (const float*)d_in[3];
    const float* be1  = (const float*)d_in[4];
    const float* We2  = (const float*)d_in[5];
    const float* be2  = (const float*)d_in[6];
    const float* Wn1  = (const float*)d_in[7];
    const float* bn1  = (const float*)d_in[8];
    const float* Wn2  = (const float*)d_in[9];
    const float* bn2  = (const float*)d_in[10];
    const float* Wc1  = (const float*)d_in[11];
    const float* bc1  = (const float*)d_in[12];
    const float* Wc2  = (const float*)d_in[13];
    const int*   eidx = (const int*)d_in[14];
    float* out = (float*)d_out;

    static bool attr_set = false;
    if (!attr_set) {
        cudaFuncSetAttribute(k_edge, cudaFuncAttributeMaxDynamicSharedMemorySize, 70 * 1024);
        attr_set = true;
    }

    k_fold<<<1, 128>>>(We2, be2, Wn1, bn1, Wc1, bc1, Wn2);
    k_tab<<<(NB + 1 + TB_BINS - 1) / TB_BINS, 256>>>(We1, be1);
    k_node<<<N_NODES / NPB, 128>>>(h, Wn1, Wc1);
    k_init<<<1024, 256>>>((const float4*)h, (const float4*)x, (float4*)out);

    // smem: 8192 (WA,WB) + WPB*1024 (gbuf) + 192 small floats
    const int smem = (8192 + WPB * 1024 + 192) * sizeof(float);  // 66304 B
    k_edge<<<296, TPB, smem>>>(dist, eidx, x, bn2, Wc2, out);
}

// round 14
// speedup vs baseline: 1.2005x; 1.0211x over previous
#include <cuda_runtime.h>
#include <cuda_fp16.h>
#include <math.h>

#define N_NODES  50000
#define N_EDGES  800000
#define NODE_DIM 64
#define EDGE_DIM 32
#define HID      128
#define EPB      8
#define TPB      256
#define WPB      (TPB / 32)
#define NB       8192          // table bins over d in [0,15], nearest-neighbor
#define TB_BINS  8

typedef unsigned long long ull;

// Per-node packed fp16 rows, 512 halves per node:
//   [0..256):  src-part, lane l: ns[4l..4l+3] at 8l, cs[4l..4l+3] at 8l+4
//   [256..512): dst-part, lane l: nd[4l..4l+3] at 8l, cd[4l..4l+3] at 8l+4
__device__ __half g_Ah[(size_t)N_NODES * 512];
// Folded edge-path weights (used only to build the table)
__device__ float g_Mn[32 * 128];
__device__ float g_Mc[32 * 128];
__device__ float g_bn[128];
__device__ float g_bc[128];
// Packed fp16 table, 256 halves per bin:
//   lane l: F[4l..4l+3] at 8l, G[4l..4l+3] at 8l+4
__device__ __half g_Th[(size_t)(NB + 1) * 256];
// Rearranged Wn2: WA[i*32+l] = Wn2[4i..4i+3][2l], WB same for 2l+1
__device__ float4 g_WA[1024];
__device__ float4 g_WB[1024];

union F4 { float4 f; ulonglong2 u; };
union F2 { float2 f; ull u; };

__device__ __forceinline__ ull pk2(float x, float y) {
    ull r; asm("mov.b64 %0,{%1,%2};" : "=l"(r) : "f"(x), "f"(y)); return r;
}
__device__ __forceinline__ void upk2(ull v, float& x, float& y) {
    asm("mov.b64 {%0,%1},%2;" : "=f"(x), "=f"(y) : "l"(v));
}
__device__ __forceinline__ ull ffma2(ull a, ull b, ull c) {
    ull d; asm("fma.rn.f32x2 %0,%1,%2,%3;" : "=l"(d) : "l"(a), "l"(b), "l"(c)); return d;
}
__device__ __forceinline__ ull fadd2(ull a, ull b) {
    ull d; asm("add.rn.f32x2 %0,%1,%2;" : "=l"(d) : "l"(a), "l"(b)); return d;
}
// half2 (packed in u32) -> f32x2 pair packed in u64
__device__ __forceinline__ ull h2f2(unsigned int h) {
    ull r;
    asm("{\n\t"
        ".reg .f16 a,b;\n\t"
        ".reg .f32 lo,hi;\n\t"
        "mov.b32 {a,b},%1;\n\t"
        "cvt.f32.f16 lo,a;\n\t"
        "cvt.f32.f16 hi,b;\n\t"
        "mov.b64 %0,{lo,hi};\n\t"
        "}" : "=l"(r) : "r"(h));
    return r;
}
// silu via MUFU tanh: silu(z) = hz + hz*tanh(hz), hz = z/2
__device__ __forceinline__ float silu1(float z) {
    float hz = 0.5f * z;
    float th;
    asm("tanh.approx.f32 %0, %1;" : "=f"(th) : "f"(hz));
    return fmaf(hz, th, hz);
}

// ---------------------------------------------------------------------------
// K0: fold edge-path weights + rearrange Wn2
// ---------------------------------------------------------------------------
__global__ void k_fold(const float* __restrict__ We2, const float* __restrict__ be2,
                       const float* __restrict__ Wn1, const float* __restrict__ bn1,
                       const float* __restrict__ Wc1, const float* __restrict__ bc1,
                       const float* __restrict__ Wn2) {
    int j = threadIdx.x;  // 0..127
    float bn = bn1[j], bc = bc1[j];
    for (int b = 0; b < 32; b++) {
        bn += be2[b] * Wn1[(128 + b) * 128 + j];
        bc += be2[b] * Wc1[(128 + b) * 128 + j];
    }
    g_bn[j] = bn;
    g_bc[j] = bc;
    for (int a = 0; a < 32; a++) {
        float sn = 0.f, sc = 0.f;
        for (int b = 0; b < 32; b++) {
            float w = We2[a * 32 + b];
            sn += w * Wn1[(128 + b) * 128 + j];
            sc += w * Wc1[(128 + b) * 128 + j];
        }
        g_Mn[a * 128 + j] = sn;
        g_Mc[a * 128 + j] = sc;
    }
    for (int idx = j; idx < 1024; idx += 128) {
        int i = idx >> 5, l = idx & 31;
        g_WA[idx] = make_float4(Wn2[(4 * i + 0) * 64 + 2 * l], Wn2[(4 * i + 1) * 64 + 2 * l],
                                Wn2[(4 * i + 2) * 64 + 2 * l], Wn2[(4 * i + 3) * 64 + 2 * l]);
        g_WB[idx] = make_float4(Wn2[(4 * i + 0) * 64 + 2 * l + 1], Wn2[(4 * i + 1) * 64 + 2 * l + 1],
                                Wn2[(4 * i + 2) * 64 + 2 * l + 1], Wn2[(4 * i + 3) * 64 + 2 * l + 1]);
    }
}

// ---------------------------------------------------------------------------
// K0b: build packed fp16 edge-path table. TB_BINS bins per block.
// ---------------------------------------------------------------------------
__global__ void k_tab(const float* __restrict__ We1, const float* __restrict__ be1) {
    __shared__ float M_sh[8192];   // Mn(4096) | Mc(4096)
    __shared__ float b_sh[256];    // bn(128) | bc(128)
    __shared__ float t_sh[32];
    int j = threadIdx.x;           // 0..255
    for (int i = j; i < 4096; i += 256) {
        M_sh[i]        = g_Mn[i];
        M_sh[4096 + i] = g_Mc[i];
    }
    if (j < 128) {
        b_sh[j]       = g_bn[j];
        b_sh[128 + j] = g_bc[j];
    }
    __syncthreads();

    const float* M = (j < 128) ? M_sh : (M_sh + 4096);
    int jj = j & 127;
    float bb = b_sh[j];
    // packed position: F element jj -> (jj/4)*8 + jj%4 ; G -> +4
    int pos = (jj >> 2) * 8 + (jj & 3) + ((j < 128) ? 0 : 4);

    for (int bi = 0; bi < TB_BINS; bi++) {
        int i = blockIdx.x * TB_BINS + bi;
        if (i > NB) break;
        float d = (15.0f / NB) * i;
        if (j < 32) {
            float z = d * We1[j] + be1[j];
            t_sh[j] = z / (1.f + __expf(-z));   // exact silu for table accuracy
        }
        __syncthreads();
        float s = bb;
#pragma unroll 8
        for (int k = 0; k < 32; k++) s += t_sh[k] * M[k * 128 + jj];
        g_Th[(size_t)i * 256 + pos] = __float2half_rn(s);
        __syncthreads();
    }
}

// ---------------------------------------------------------------------------
// K1: per-node precompute, f32x2 math, packed fp16 output. 128 thr, NPB=16.
// ---------------------------------------------------------------------------
#define NPB 16
__global__ void k_node(const float* __restrict__ h,
                       const float* __restrict__ Wn1,
                       const float* __restrict__ Wc1) {
    __shared__ ull h2[NPB * 64];   // duplicated {h,h} pairs
    int node0 = blockIdx.x * NPB;
    for (int i = threadIdx.x; i < NPB * 64; i += 128) {
        float hv = h[node0 * 64 + i];
        h2[i] = pk2(hv, hv);
    }
    __syncthreads();
    int j = threadIdx.x;
    int m = j >> 5;               // 0=ns 1=nd 2=cs 3=cd
    int c = (j & 31) * 4;
    const float* W = ((m & 2) ? Wc1 : Wn1) + ((m & 1) ? 64 * 128 : 0);
    // packed half-offset within node row
    int off = ((m & 1) ? 256 : 0) + (j & 31) * 8 + ((m & 2) ? 4 : 0);

    ull a0[NPB], a1[NPB];
#pragma unroll
    for (int n = 0; n < NPB; n++) { a0[n] = 0ull; a1[n] = 0ull; }
#pragma unroll 4
    for (int k = 0; k < 64; k++) {
        F4 w; w.f = *(const float4*)&W[k * 128 + c];
#pragma unroll
        for (int n = 0; n < NPB; n++) {
            ull hv = h2[n * 64 + k];
            a0[n] = ffma2(hv, w.u.x, a0[n]);
            a1[n] = ffma2(hv, w.u.y, a1[n]);
        }
    }
#pragma unroll
    for (int n = 0; n < NPB; n++) {
        float x0, x1, x2, x3;
        upk2(a0[n], x0, x1);
        upk2(a1[n], x2, x3);
        __half2 hA = __float22half2_rn(make_float2(x0, x1));
        __half2 hB = __float22half2_rn(make_float2(x2, x3));
        uint2 st;
        st.x = *(unsigned int*)&hA;
        st.y = *(unsigned int*)&hB;
        *(uint2*)&g_Ah[(size_t)(node0 + n) * 512 + off] = st;
    }
}

// ---------------------------------------------------------------------------
// K2: initialize output with (h, x), float4-vectorized
// ---------------------------------------------------------------------------
__global__ void k_init(const float4* __restrict__ h4, const float4* __restrict__ x4,
                       float4* __restrict__ out4) {
    const int nh4  = N_NODES * 16;          // 800000
    const int tot4 = nh4 + N_NODES * 3 / 4; // 837500
    for (int i = blockIdx.x * blockDim.x + threadIdx.x; i < tot4; i += gridDim.x * blockDim.x)
        out4[i] = (i < nh4) ? h4[i] : x4[i - nh4];
}

// ---------------------------------------------------------------------------
// K3: edge kernel. 3 packed LDG.128 gathers per edge (src, dst, table).
// ---------------------------------------------------------------------------
__global__ void __launch_bounds__(TPB, 2)
k_edge(const float* __restrict__ dist,
       const int*   __restrict__ eidx,
       const float* __restrict__ x,
       const float* __restrict__ bn2,
       const float* __restrict__ Wc2,
       float* __restrict__ out) {
    extern __shared__ float sm[];
    float4* WA_sh = (float4*)sm;               // 1024 f4
    float4* WB_sh = WA_sh + 1024;              // 1024 f4
    float*  gbuf  = (float*)(WB_sh + 1024);    // WPB warps * 1024
    float*  Wc2_sh = gbuf + WPB * 1024;        // 128
    float*  bn2_sh = Wc2_sh + 128;             // 64

    for (int i = threadIdx.x; i < 1024; i += blockDim.x) {
        WA_sh[i] = g_WA[i];
        WB_sh[i] = g_WB[i];
    }
    if (threadIdx.x < 128) Wc2_sh[threadIdx.x] = Wc2[threadIdx.x];
    if (threadIdx.x < 64)  bn2_sh[threadIdx.x] = bn2[threadIdx.x];
    __syncthreads();

    const int lane = threadIdx.x & 31;
    const int wib  = threadIdx.x >> 5;
    const int gw   = blockIdx.x * WPB + wib;
    const int nw   = gridDim.x * WPB;

    F4 wc2_4; wc2_4.f = *(const float4*)&Wc2_sh[4 * lane];
    const float2 bn2_2 = *(const float2*)&bn2_sh[2 * lane];
    float* gb = gbuf + wib * 1024;
    const uint4* A4h = (const uint4*)g_Ah;     // 64 uint4 per node (32 src + 32 dst)
    const uint4* T4h = (const uint4*)g_Th;     // 32 uint4 per table row
    const float4* gb4 = (const float4*)gb;
    float* out_x = out + (size_t)N_NODES * 64;

    for (int base = gw * EPB; base < N_EDGES; base += nw * EPB) {
        int src[EPB], dstn[EPB];
        float cw[EPB];

        // ---- per-edge: 3 packed gathers, both MLP hiddens ----
#pragma unroll
        for (int ee = 0; ee < EPB; ee++) {
            int e = base + ee;
            float d = dist[e];
            int s  = eidx[e];
            int dd = eidx[N_EDGES + e];
            src[ee] = s; dstn[ee] = dd;

            float p = d * (NB / 15.0f) + 0.5f;
            int i0 = (int)p;
            i0 = max(0, min(i0, NB));

            uint4 sv = A4h[(size_t)s  * 64 + lane];        // ns (x,y) | cs (z,w)
            uint4 dv = A4h[(size_t)dd * 64 + 32 + lane];   // nd (x,y) | cd (z,w)
            uint4 tv = T4h[(size_t)i0 * 32 + lane];        // F  (x,y) | G  (z,w)

            // node-MLP hidden
            {
                ull px = fadd2(fadd2(h2f2(sv.x), h2f2(dv.x)), h2f2(tv.x));
                ull py = fadd2(fadd2(h2f2(sv.y), h2f2(dv.y)), h2f2(tv.y));
                float p0, p1, p2, p3;
                upk2(px, p0, p1);
                upk2(py, p2, p3);
                float4 gn = make_float4(silu1(p0), silu1(p1), silu1(p2), silu1(p3));
                *(float4*)&gb[ee * 128 + 4 * lane] = gn;
            }
            // coord-MLP hidden -> scalar cw
            {
                ull px = fadd2(fadd2(h2f2(sv.z), h2f2(dv.z)), h2f2(tv.z));
                ull py = fadd2(fadd2(h2f2(sv.w), h2f2(dv.w)), h2f2(tv.w));
                float p0, p1, p2, p3;
                upk2(px, p0, p1);
                upk2(py, p2, p3);
                float ss = silu1(p0) * wc2_4.f.x + silu1(p1) * wc2_4.f.y
                         + silu1(p2) * wc2_4.f.z + silu1(p3) * wc2_4.f.w;
#pragma unroll
                for (int off = 16; off > 0; off >>= 1)
                    ss += __shfl_xor_sync(0xffffffffu, ss, off);
                cw[ee] = ss;
            }
        }

        // ---- coord scatter (lanes 0..7, one edge each) ----
        if (lane < EPB) {
            float mycw = cw[0]; int ms = src[0], md = dstn[0];
#pragma unroll
            for (int ee = 1; ee < EPB; ee++)
                if (lane == ee) { mycw = cw[ee]; ms = src[ee]; md = dstn[ee]; }
            float dx = x[ms * 3 + 0] - x[md * 3 + 0];
            float dy = x[ms * 3 + 1] - x[md * 3 + 1];
            float dz = x[ms * 3 + 2] - x[md * 3 + 2];
            float len = fmaxf(sqrtf(dx * dx + dy * dy + dz * dz), 1e-8f);
            float inv = mycw / len;
            float* ox = out_x + (size_t)md * 3;
            atomicAdd(&ox[0], dx * inv);
            atomicAdd(&ox[1], dy * inv);
            atomicAdd(&ox[2], dz * inv);
        }
        __syncwarp();

        // ---- phase 2: gn(128) @ Wn2 -> 64 ----
        ull macA[EPB], macB[EPB];
#pragma unroll
        for (int ee = 0; ee < EPB; ee++) {
            macA[ee] = pk2(bn2_2.x, 0.f);
            macB[ee] = pk2(bn2_2.y, 0.f);
        }
#pragma unroll
        for (int i = 0; i < 32; i++) {
            F4 wA; wA.f = WA_sh[i * 32 + lane];
            F4 wB; wB.f = WB_sh[i * 32 + lane];
#pragma unroll
            for (int ee = 0; ee < EPB; ee++) {
                F4 g; g.f = gb4[ee * 32 + i];  // broadcast
                macA[ee] = ffma2(g.u.x, wA.u.x, macA[ee]);
                macA[ee] = ffma2(g.u.y, wA.u.y, macA[ee]);
                macB[ee] = ffma2(g.u.x, wB.u.x, macB[ee]);
                macB[ee] = ffma2(g.u.y, wB.u.y, macB[ee]);
            }
        }

        // ---- node message scatter (scalar atomics: proven REDG fast path) ----
#pragma unroll
        for (int ee = 0; ee < EPB; ee++) {
            float a0, a1, b0, b1;
            upk2(macA[ee], a0, a1);
            upk2(macB[ee], b0, b1);
            float* oh = out + (size_t)dstn[ee] * 64;
            atomicAdd(&oh[2 * lane],     a0 + a1);
            atomicAdd(&oh[2 * lane + 1], b0 + b1);
        }
        __syncwarp();   // gbuf reuse safety across iterations
    }
}

// ---------------------------------------------------------------------------
extern "C" void kernel_launch(void* const* d_in, const int* in_sizes, int n_in,
                              void* d_out, int out_size) {
    const float* h    = (const float*)d_in[0];
    const float* x    = (const float*)d_in[1];
    const float* dist = (const float*)d_in[2];
    const float* We1  = (const float*)d_in[3];
    const float* be1  = (const float*)d_in[4];
    const float* We2  = (const float*)d_in[5];
    const float* be2  = (const float*)d_in[6];
    const float* Wn1  = (const float*)d_in[7];
    const float* bn1  = (const float*)d_in[8];
    const float* Wn2  = (const float*)d_in[9];
    const float* bn2  = (const float*)d_in[10];
    const float* Wc1  = (const float*)d_in[11];
    const float* bc1  = (const float*)d_in[12];
    const float* Wc2  = (const float*)d_in[13];
    const int*   eidx = (const int*)d_in[14];
    float* out = (float*)d_out;

    static bool attr_set = false;
    if (!attr_set) {
        cudaFuncSetAttribute(k_edge, cudaFuncAttributeMaxDynamicSharedMemorySize, 70 * 1024);
        attr_set = true;
    }

    k_fold<<<1, 128>>>(We2, be2, Wn1, bn1, Wc1, bc1, Wn2);
    k_tab<<<(NB + 1 + TB_BINS - 1) / TB_BINS, 256>>>(We1, be1);
    k_node<<<N_NODES / NPB, 128>>>(h, Wn1, Wc1);
    k_init<<<1024, 256>>>((const float4*)h, (const float4*)x, (float4*)out);

    // smem: 8192 (WA,WB) + WPB*1024 (gbuf) + 192 small floats
    const int smem = (8192 + WPB * 1024 + 192) * sizeof(float);  // 66304 B
    k_edge<<<296, TPB, smem>>>(dist, eidx, x, bn2, Wc2, out);
}

// round 15
// speedup vs baseline: 1.7264x; 1.4381x over previous
#include <cuda_runtime.h>
#include <cuda_fp16.h>
#include <math.h>

#define N_NODES  50000
#define N_EDGES  800000
#define NODE_DIM 64
#define EDGE_DIM 32
#define HID      128
#define EPG      16            // edges per warp group (one m16 MMA tile)
#define TPB      256
#define WPB      (TPB / 32)
#define NB       8192          // table bins over d in [0,15], nearest-neighbor
#define TB_BINS  8

typedef unsigned long long ull;

// Per-node packed fp16 rows, 512 halves per node:
//   [0..256):  src-part, lane l: ns[4l..4l+3] at 8l, cs[4l..4l+3] at 8l+4
//   [256..512): dst-part, lane l: nd[4l..4l+3] at 8l, cd[4l..4l+3] at 8l+4
__device__ __half g_Ah[(size_t)N_NODES * 512];
// Folded edge-path weights (used only to build the table)
__device__ float g_Mn[32 * 128];
__device__ float g_Mc[32 * 128];
__device__ float g_bn[128];
__device__ float g_bc[128];
// Packed fp16 table, 256 halves per bin: lane l: F[4l..4l+3] at 8l, G at 8l+4
__device__ __half g_Th[(size_t)(NB + 1) * 256];

union F4 { float4 f; ulonglong2 u; };

__device__ __forceinline__ ull pk2(float x, float y) {
    ull r; asm("mov.b64 %0,{%1,%2};" : "=l"(r) : "f"(x), "f"(y)); return r;
}
__device__ __forceinline__ void upk2(ull v, float& x, float& y) {
    asm("mov.b64 {%0,%1},%2;" : "=f"(x), "=f"(y) : "l"(v));
}
__device__ __forceinline__ ull fadd2(ull a, ull b) {
    ull d; asm("add.rn.f32x2 %0,%1,%2;" : "=l"(d) : "l"(a), "l"(b)); return d;
}
__device__ __forceinline__ ull h2f2(unsigned int h) {
    ull r;
    asm("{\n\t"
        ".reg .f16 a,b;\n\t"
        ".reg .f32 lo,hi;\n\t"
        "mov.b32 {a,b},%1;\n\t"
        "cvt.f32.f16 lo,a;\n\t"
        "cvt.f32.f16 hi,b;\n\t"
        "mov.b64 %0,{lo,hi};\n\t"
        "}" : "=l"(r) : "r"(h));
    return r;
}
__device__ __forceinline__ float silu1(float z) {
    float hz = 0.5f * z;
    float th;
    asm("tanh.approx.f32 %0, %1;" : "=f"(th) : "f"(hz));
    return fmaf(hz, th, hz);
}
__device__ __forceinline__ unsigned int smem_u32(const void* p) {
    unsigned int a;
    asm("{ .reg .u64 t; cvta.to.shared.u64 t, %1; cvt.u32.u64 %0, t; }" : "=r"(a) : "l"(p));
    return a;
}

// ---------------------------------------------------------------------------
// K0: fold edge-path weights
// ---------------------------------------------------------------------------
__global__ void k_fold(const float* __restrict__ We2, const float* __restrict__ be2,
                       const float* __restrict__ Wn1, const float* __restrict__ bn1,
                       const float* __restrict__ Wc1, const float* __restrict__ bc1) {
    int j = threadIdx.x;  // 0..127
    float bn = bn1[j], bc = bc1[j];
    for (int b = 0; b < 32; b++) {
        bn += be2[b] * Wn1[(128 + b) * 128 + j];
        bc += be2[b] * Wc1[(128 + b) * 128 + j];
    }
    g_bn[j] = bn;
    g_bc[j] = bc;
    for (int a = 0; a < 32; a++) {
        float sn = 0.f, sc = 0.f;
        for (int b = 0; b < 32; b++) {
            float w = We2[a * 32 + b];
            sn += w * Wn1[(128 + b) * 128 + j];
            sc += w * Wc1[(128 + b) * 128 + j];
        }
        g_Mn[a * 128 + j] = sn;
        g_Mc[a * 128 + j] = sc;
    }
}

// ---------------------------------------------------------------------------
// K0b: build packed fp16 edge-path table. TB_BINS bins per block.
// ---------------------------------------------------------------------------
__global__ void k_tab(const float* __restrict__ We1, const float* __restrict__ be1) {
    __shared__ float M_sh[8192];
    __shared__ float b_sh[256];
    __shared__ float t_sh[32];
    int j = threadIdx.x;
    for (int i = j; i < 4096; i += 256) {
        M_sh[i]        = g_Mn[i];
        M_sh[4096 + i] = g_Mc[i];
    }
    if (j < 128) {
        b_sh[j]       = g_bn[j];
        b_sh[128 + j] = g_bc[j];
    }
    __syncthreads();

    const float* M = (j < 128) ? M_sh : (M_sh + 4096);
    int jj = j & 127;
    float bb = b_sh[j];
    int pos = (jj >> 2) * 8 + (jj & 3) + ((j < 128) ? 0 : 4);

    for (int bi = 0; bi < TB_BINS; bi++) {
        int i = blockIdx.x * TB_BINS + bi;
        if (i > NB) break;
        float d = (15.0f / NB) * i;
        if (j < 32) {
            float z = d * We1[j] + be1[j];
            t_sh[j] = z / (1.f + __expf(-z));
        }
        __syncthreads();
        float s = bb;
#pragma unroll 8
        for (int k = 0; k < 32; k++) s += t_sh[k] * M[k * 128 + jj];
        g_Th[(size_t)i * 256 + pos] = __float2half_rn(s);
        __syncthreads();
    }
}

// ---------------------------------------------------------------------------
// K1: per-node precompute, packed fp16 output. 128 thr, NPB=16.
// ---------------------------------------------------------------------------
#define NPB 16
__global__ void k_node(const float* __restrict__ h,
                       const float* __restrict__ Wn1,
                       const float* __restrict__ Wc1) {
    __shared__ ull h2[NPB * 64];
    int node0 = blockIdx.x * NPB;
    for (int i = threadIdx.x; i < NPB * 64; i += 128) {
        float hv = h[node0 * 64 + i];
        h2[i] = pk2(hv, hv);
    }
    __syncthreads();
    int j = threadIdx.x;
    int m = j >> 5;
    int c = (j & 31) * 4;
    const float* W = ((m & 2) ? Wc1 : Wn1) + ((m & 1) ? 64 * 128 : 0);
    int off = ((m & 1) ? 256 : 0) + (j & 31) * 8 + ((m & 2) ? 4 : 0);

    ull a0[NPB], a1[NPB];
#pragma unroll
    for (int n = 0; n < NPB; n++) { a0[n] = 0ull; a1[n] = 0ull; }
#pragma unroll 4
    for (int k = 0; k < 64; k++) {
        F4 w; w.f = *(const float4*)&W[k * 128 + c];
#pragma unroll
        for (int n = 0; n < NPB; n++) {
            ull hv = h2[n * 64 + k];
            asm("fma.rn.f32x2 %0,%1,%2,%0;" : "+l"(a0[n]) : "l"(hv), "l"(w.u.x));
            asm("fma.rn.f32x2 %0,%1,%2,%0;" : "+l"(a1[n]) : "l"(hv), "l"(w.u.y));
        }
    }
#pragma unroll
    for (int n = 0; n < NPB; n++) {
        float x0, x1, x2, x3;
        upk2(a0[n], x0, x1);
        upk2(a1[n], x2, x3);
        __half2 hA = __float22half2_rn(make_float2(x0, x1));
        __half2 hB = __float22half2_rn(make_float2(x2, x3));
        uint2 st;
        st.x = *(unsigned int*)&hA;
        st.y = *(unsigned int*)&hB;
        *(uint2*)&g_Ah[(size_t)(node0 + n) * 512 + off] = st;
    }
}

// ---------------------------------------------------------------------------
// K2: initialize output with (h, x), float4-vectorized
// ---------------------------------------------------------------------------
__global__ void k_init(const float4* __restrict__ h4, const float4* __restrict__ x4,
                       float4* __restrict__ out4) {
    const int nh4  = N_NODES * 16;
    const int tot4 = nh4 + N_NODES * 3 / 4;
    for (int i = blockIdx.x * blockDim.x + threadIdx.x; i < tot4; i += gridDim.x * blockDim.x)
        out4[i] = (i < nh4) ? h4[i] : x4[i - nh4];
}

// ---------------------------------------------------------------------------
// K3: edge kernel. Phase1: gathers+silu -> fp16 smem tile. Phase2: HMMA GEMM.
// smem (halves): Bt[64*136] | A[WPB*16*136] ; then floats Wc2[128], bn2[64]
// ---------------------------------------------------------------------------
#define BT_H  (64 * 136)            // 8704 halves
#define AW_H  (16 * 136)            // 2176 halves per warp
#define SMEM_BYTES (2 * (BT_H + WPB * AW_H) + 128 * 4 + 64 * 4)

__global__ void __launch_bounds__(TPB, 2)
k_edge(const float* __restrict__ dist,
       const int*   __restrict__ eidx,
       const float* __restrict__ x,
       const float* __restrict__ bn2,
       const float* __restrict__ Wc2,
       const float* __restrict__ Wn2,
       float* __restrict__ out) {
    extern __shared__ __half smh[];
    __half* Bt_sh = smh;                       // [64][136] = Wn2^T fp16
    __half* A_all = smh + BT_H;
    float*  Wc2_sh = (float*)(smh + BT_H + WPB * AW_H);
    float*  bn2_sh = Wc2_sh + 128;

    // Bt[n][k] = Wn2[k][n]
    for (int idx = threadIdx.x; idx < 8192; idx += TPB) {
        int n = idx >> 7, k = idx & 127;
        Bt_sh[n * 136 + k] = __float2half_rn(Wn2[k * 64 + n]);
    }
    if (threadIdx.x < 128) Wc2_sh[threadIdx.x] = Wc2[threadIdx.x];
    if (threadIdx.x < 64)  bn2_sh[threadIdx.x] = bn2[threadIdx.x];
    __syncthreads();

    const int lane = threadIdx.x & 31;
    const int wib  = threadIdx.x >> 5;
    const int gw   = blockIdx.x * WPB + wib;
    const int nw   = gridDim.x * WPB;

    F4 wc2_4; wc2_4.f = *(const float4*)&Wc2_sh[4 * lane];
    // bias pairs for the 8 n-tiles this lane owns (cols 2*(lane&3), +1)
    float2 bn2p[8];
#pragma unroll
    for (int nt = 0; nt < 8; nt++)
        bn2p[nt] = *(const float2*)&bn2_sh[nt * 8 + 2 * (lane & 3)];

    __half* A_w = A_all + wib * AW_H;
    const unsigned int A_base  = smem_u32(A_w);
    const unsigned int Bt_base = smem_u32(Bt_sh);
    const unsigned int a_sel = A_base + (lane & 15) * 272 + (lane >> 4) * 16;
    const int t16 = lane & 15;
    const unsigned int b_sel = Bt_base + (t16 & 7) * 272 + (t16 >> 3) * 16;

    const uint4* A4h = (const uint4*)g_Ah;     // 64 uint4 per node
    const uint4* T4h = (const uint4*)g_Th;     // 32 uint4 per table row
    float* out_x = out + (size_t)N_NODES * 64;

    for (int base = gw * EPG; base < N_EDGES; base += nw * EPG) {

        // ---- phase 1: two 8-edge halves (proven), gn stored fp16 ----
#pragma unroll 1
        for (int hf = 0; hf < 2; hf++) {
            int src8[8], dst8[8];
            float cw[8];
#pragma unroll
            for (int ee = 0; ee < 8; ee++) {
                int e = base + hf * 8 + ee;
                float d = dist[e];
                int s  = eidx[e];
                int dd = eidx[N_EDGES + e];
                src8[ee] = s; dst8[ee] = dd;

                float p = d * (NB / 15.0f) + 0.5f;
                int i0 = (int)p;
                i0 = max(0, min(i0, NB));

                uint4 sv = A4h[(size_t)s  * 64 + lane];
                uint4 dv = A4h[(size_t)dd * 64 + 32 + lane];
                uint4 tv = T4h[(size_t)i0 * 32 + lane];

                // node-MLP hidden -> silu -> fp16 A tile
                {
                    ull px = fadd2(fadd2(h2f2(sv.x), h2f2(dv.x)), h2f2(tv.x));
                    ull py = fadd2(fadd2(h2f2(sv.y), h2f2(dv.y)), h2f2(tv.y));
                    float p0, p1, p2, p3;
                    upk2(px, p0, p1);
                    upk2(py, p2, p3);
                    __half2 h0 = __float22half2_rn(make_float2(silu1(p0), silu1(p1)));
                    __half2 h1 = __float22half2_rn(make_float2(silu1(p2), silu1(p3)));
                    uint2 st;
                    st.x = *(unsigned int*)&h0;
                    st.y = *(unsigned int*)&h1;
                    *(uint2*)&A_w[(hf * 8 + ee) * 136 + lane * 4] = st;
                }
                // coord-MLP hidden -> scalar cw
                {
                    ull px = fadd2(fadd2(h2f2(sv.z), h2f2(dv.z)), h2f2(tv.z));
                    ull py = fadd2(fadd2(h2f2(sv.w), h2f2(dv.w)), h2f2(tv.w));
                    float p0, p1, p2, p3;
                    upk2(px, p0, p1);
                    upk2(py, p2, p3);
                    float ss = silu1(p0) * wc2_4.f.x + silu1(p1) * wc2_4.f.y
                             + silu1(p2) * wc2_4.f.z + silu1(p3) * wc2_4.f.w;
#pragma unroll
                    for (int off = 16; off > 0; off >>= 1)
                        ss += __shfl_xor_sync(0xffffffffu, ss, off);
                    cw[ee] = ss;
                }
            }

            // coord scatter (lanes 0..7)
            if (lane < 8) {
                float mycw = cw[0]; int ms = src8[0], md = dst8[0];
#pragma unroll
                for (int ee = 1; ee < 8; ee++)
                    if (lane == ee) { mycw = cw[ee]; ms = src8[ee]; md = dst8[ee]; }
                float dx = x[ms * 3 + 0] - x[md * 3 + 0];
                float dy = x[ms * 3 + 1] - x[md * 3 + 1];
                float dz = x[ms * 3 + 2] - x[md * 3 + 2];
                float len = fmaxf(sqrtf(dx * dx + dy * dy + dz * dz), 1e-8f);
                float inv = mycw / len;
                float* ox = out_x + (size_t)md * 3;
                atomicAdd(&ox[0], dx * inv);
                atomicAdd(&ox[1], dy * inv);
                atomicAdd(&ox[2], dz * inv);
            }
        }
        __syncwarp();   // all gn stores visible before ldmatrix

        // ---- phase 2: m16 x n64 x k128 HMMA ----
        float c0[8], c1[8], c2[8], c3[8];
#pragma unroll
        for (int nt = 0; nt < 8; nt++) {
            c0[nt] = bn2p[nt].x; c1[nt] = bn2p[nt].y;
            c2[nt] = bn2p[nt].x; c3[nt] = bn2p[nt].y;
        }
#pragma unroll
        for (int ks = 0; ks < 8; ks++) {
            unsigned int a0, a1, a2, a3;
            asm volatile("ldmatrix.sync.aligned.m8n8.x4.shared.b16 {%0,%1,%2,%3}, [%4];"
                         : "=r"(a0), "=r"(a1), "=r"(a2), "=r"(a3)
                         : "r"(a_sel + ks * 32));
#pragma unroll
            for (int nt = 0; nt < 8; nt++) {
                unsigned int b0, b1;
                asm volatile("ldmatrix.sync.aligned.m8n8.x2.shared.b16 {%0,%1}, [%2];"
                             : "=r"(b0), "=r"(b1)
                             : "r"(b_sel + nt * 2176 + ks * 32));
                asm volatile("mma.sync.aligned.m16n8k16.row.col.f32.f16.f16.f32 "
                             "{%0,%1,%2,%3}, {%4,%5,%6,%7}, {%8,%9}, {%0,%1,%2,%3};"
                             : "+f"(c0[nt]), "+f"(c1[nt]), "+f"(c2[nt]), "+f"(c3[nt])
                             : "r"(a0), "r"(a1), "r"(a2), "r"(a3), "r"(b0), "r"(b1));
            }
        }

        // ---- scatter: lane holds rows lane/4 and lane/4+8, cols 2*(lane&3),+1 ----
        {
            int e0 = base + (lane >> 2);
            int d0 = eidx[N_EDGES + e0];
            int d1 = eidx[N_EDGES + e0 + 8];
            int coloff = 2 * (lane & 3);
            float* p0 = out + (size_t)d0 * 64 + coloff;
            float* p1 = out + (size_t)d1 * 64 + coloff;
#pragma unroll
            for (int nt = 0; nt < 8; nt++) {
                atomicAdd(p0 + nt * 8,     c0[nt]);
                atomicAdd(p0 + nt * 8 + 1, c1[nt]);
                atomicAdd(p1 + nt * 8,     c2[nt]);
                atomicAdd(p1 + nt * 8 + 1, c3[nt]);
            }
        }
        __syncwarp();   // A tile reuse safety
    }
}

// ---------------------------------------------------------------------------
extern "C" void kernel_launch(void* const* d_in, const int* in_sizes, int n_in,
                              void* d_out, int out_size) {
    const float* h    = (const float*)d_in[0];
    const float* x    = (const float*)d_in[1];
    const float* dist = (const float*)d_in[2];
    const float* We1  = (const float*)d_in[3];
    const float* be1  = (const float*)d_in[4];
    const float* We2  = (const float*)d_in[5];
    const float* be2  = (const float*)d_in[6];
    const float* Wn1  = (const float*)d_in[7];
    const float* bn1  = (const float*)d_in[8];
    const float* Wn2  = (const float*)d_in[9];
    const float* bn2  = (const float*)d_in[10];
    const float* Wc1  = (const float*)d_in[11];
    const float* bc1  = (const float*)d_in[12];
    const float* Wc2  = (const float*)d_in[13];
    const int*   eidx = (const int*)d_in[14];
    float* out = (float*)d_out;

    static bool attr_set = false;
    if (!attr_set) {
        cudaFuncSetAttribute(k_edge, cudaFuncAttributeMaxDynamicSharedMemorySize, 60 * 1024);
        attr_set = true;
    }

    k_fold<<<1, 128>>>(We2, be2, Wn1, bn1, Wc1, bc1);
    k_tab<<<(NB + 1 + TB_BINS - 1) / TB_BINS, 256>>>(We1, be1);
    k_node<<<N_NODES / NPB, 128>>>(h, Wn1, Wc1);
    k_init<<<1024, 256>>>((const float4*)h, (const float4*)x, (float4*)out);

    k_edge<<<296, TPB, SMEM_BYTES>>>(dist, eidx, x, bn2, Wc2, Wn2, out);
}